// round 15
// baseline (speedup 1.0000x reference)
#include <cuda_runtime.h>
#include <cuda_bf16.h>
#include <math.h>
#include <cstdint>

// Problem constants
#define BB 2
#define SS 2048
#define HH 2048
#define NH 16
#define NKV 4
#define HD 128
#define NE 8
#define II 4096
#define TT (BB*SS)          // 4096 tokens
#define QD (NH*HD)          // 2048
#define KVD (NKV*HD)        // 512
#define NSLOTS (TT*2)       // 8192 expert assignments

// GEMM pipeline config: BK=16, dense rows of 16 floats
#define NSTAGE 4
#define BSTG 2048                      // floats per operand per stage (128*16)
#define TC_SMEM_BYTES (NSTAGE * 2 * BSTG * 4)   // 65536 bytes
#define GU_SMEM_BYTES (NSTAGE * 3 * BSTG * 4)   // 98304 bytes (A, Bg, Bu)

// ---------------- static scratch ----------------------------------------------
__device__ float g_x[(size_t)TT*HH];
__device__ float g_q[(size_t)TT*QD];
__device__ float g_k[(size_t)TT*KVD];
__device__ float g_v[(size_t)TT*KVD];
__device__ float g_scores[(size_t)BB*NH*SS*SS];
__device__ float g_attn[(size_t)TT*QD];
__device__ float g_hid2[(size_t)TT*HH];
__device__ float g_xg[(size_t)NSLOTS*HH];
__device__ float g_act[(size_t)NSLOTS*II];
__device__ float g_y[(size_t)NSLOTS*HH];
__device__ int   g_topi[NSLOTS];
__device__ float g_topw[NSLOTS];
__device__ int   g_counts[NE];
__device__ int   g_offsets[NE];
__device__ int   g_cursor[NE];
__device__ int   g_tok[NSLOTS];
__device__ int   g_slot[NSLOTS];
// transposed (and tf32-prerounded) operands
__device__ float g_wqT[(size_t)QD*HH];
__device__ float g_wkT[(size_t)KVD*HH];
__device__ float g_wvT[(size_t)KVD*HH];
__device__ float g_woT[(size_t)HH*QD];
__device__ float g_gwT[(size_t)NE*II*HH];
__device__ float g_uwT[(size_t)NE*II*HH];
__device__ float g_dwT[(size_t)NE*HH*II];
__device__ float g_vT[(size_t)BB*NKV*HD*SS];

// ---------------- helpers -------------------------------------------------------
__device__ __forceinline__ uint32_t smem_u32(const void* p) {
    uint32_t a;
    asm("{ .reg .u64 t; cvta.to.shared.u64 t, %1; cvt.u32.u64 %0, t; }" : "=r"(a) : "l"(p));
    return a;
}
__device__ __forceinline__ float to_tf32(float x) {
    float r; asm("cvt.rna.tf32.f32 %0, %1;" : "=f"(r) : "f"(x)); return r;
}
__device__ __forceinline__ void mma_tf32(float* d, const uint32_t* a, const uint32_t* b) {
    asm volatile(
        "mma.sync.aligned.m16n8k8.row.col.f32.tf32.tf32.f32 "
        "{%0,%1,%2,%3}, {%4,%5,%6,%7}, {%8,%9}, {%0,%1,%2,%3};"
        : "+f"(d[0]), "+f"(d[1]), "+f"(d[2]), "+f"(d[3])
        : "r"(a[0]), "r"(a[1]), "r"(a[2]), "r"(a[3]), "r"(b[0]), "r"(b[1]));
}
__device__ __forceinline__ void cp16(uint32_t s, const void* g, int sz) {
    asm volatile("cp.async.cg.shared.global [%0], [%1], 16, %2;"
                 :: "r"(s), "l"(g), "r"(sz) : "memory");
}
#define CP_COMMIT() asm volatile("cp.async.commit_group;" ::: "memory")
#define CP_WAIT(N)  asm volatile("cp.async.wait_group %0;" :: "n"(N) : "memory")

// ---------------- tf32 MMA GEMM core ------------------------------------------
// C[128x128] = A[128xK] * B[N=128 rows][K] (both K-contiguous, tf32-prerounded).
template<bool ROUND>
__device__ __forceinline__ void mma_core(
    const float* __restrict__ A, int lda, int Mrem,
    const float* __restrict__ B, int ldb,
    const float* __restrict__ D, float* __restrict__ C, int ldc, int K)
{
    extern __shared__ __align__(16) float smemf[];
    uint32_t sbase = smem_u32(smemf);
    int tid = threadIdx.x;
    int wid = tid >> 5;
    int lane = tid & 31;

    int ar  = tid >> 1;
    int ako = (tid & 1) * 8;
    int a_sz = (ar < Mrem) ? 16 : 0;
    const float* agbase = A + (size_t)ar * lda + ako;
    const float* bgbase = B + (size_t)ar * ldb + ako;
    uint32_t soff = (uint32_t)(ar * 16 + ako) * 4;

    int wm = (wid >> 2) * 64;
    int wn = (wid & 3) * 32;
    int qrow = lane >> 2;
    int kq4 = (lane & 3) * 4;

    float acc[4][4][4];
    #pragma unroll
    for (int i = 0; i < 4; i++)
        #pragma unroll
        for (int j = 0; j < 4; j++)
            #pragma unroll
            for (int c = 0; c < 4; c++) acc[i][j][c] = 0.f;

    int KT = K >> 4;

    #pragma unroll
    for (int c = 0; c < NSTAGE - 1; c++) {
        int kc = c << 4;
        uint32_t ab = sbase + (uint32_t)c * (BSTG * 4);
        uint32_t bb = sbase + (uint32_t)(NSTAGE + c) * (BSTG * 4);
        cp16(ab + soff,      agbase + kc,     a_sz);
        cp16(ab + soff + 16, agbase + kc + 4, a_sz);
        cp16(bb + soff,      bgbase + kc,     16);
        cp16(bb + soff + 16, bgbase + kc + 4, 16);
        CP_COMMIT();
    }

    for (int kt = 0; kt < KT; kt++) {
        CP_WAIT(NSTAGE - 2);
        __syncthreads();

        int nc = kt + NSTAGE - 1;
        if (nc < KT) {
            int s = nc & (NSTAGE - 1);
            int kc = nc << 4;
            uint32_t ab = sbase + (uint32_t)s * (BSTG * 4);
            uint32_t bb = sbase + (uint32_t)(NSTAGE + s) * (BSTG * 4);
            cp16(ab + soff,      agbase + kc,     a_sz);
            cp16(ab + soff + 16, agbase + kc + 4, a_sz);
            cp16(bb + soff,      bgbase + kc,     16);
            cp16(bb + soff + 16, bgbase + kc + 4, 16);
        }
        CP_COMMIT();

        int s = kt & (NSTAGE - 1);
        const float* As = smemf + (size_t)s * BSTG;
        const float* Bs = smemf + (size_t)(NSTAGE + s) * BSTG;

        float4 av0[4], av1[4], bv[4];
        #pragma unroll
        for (int mt = 0; mt < 4; mt++) {
            const float* ab = As + (wm + mt*16 + qrow) * 16 + kq4;
            av0[mt] = *(const float4*)ab;
            av1[mt] = *(const float4*)(ab + 128);
        }
        #pragma unroll
        for (int nt = 0; nt < 4; nt++)
            bv[nt] = *(const float4*)(Bs + (wn + nt*8 + qrow) * 16 + kq4);

        #pragma unroll
        for (int mt = 0; mt < 4; mt++) {
            uint32_t afr[4] = { __float_as_uint(av0[mt].x), __float_as_uint(av1[mt].x),
                                __float_as_uint(av0[mt].y), __float_as_uint(av1[mt].y) };
            #pragma unroll
            for (int nt = 0; nt < 4; nt++) {
                uint32_t bfr[2] = { __float_as_uint(bv[nt].x), __float_as_uint(bv[nt].y) };
                mma_tf32(acc[mt][nt], afr, bfr);
            }
        }
        #pragma unroll
        for (int mt = 0; mt < 4; mt++) {
            uint32_t afr[4] = { __float_as_uint(av0[mt].z), __float_as_uint(av1[mt].z),
                                __float_as_uint(av0[mt].w), __float_as_uint(av1[mt].w) };
            #pragma unroll
            for (int nt = 0; nt < 4; nt++) {
                uint32_t bfr[2] = { __float_as_uint(bv[nt].z), __float_as_uint(bv[nt].w) };
                mma_tf32(acc[mt][nt], afr, bfr);
            }
        }
    }

    int kq = lane & 3;
    #pragma unroll
    for (int mt = 0; mt < 4; mt++) {
        int r0 = wm + mt*16 + qrow;
        #pragma unroll
        for (int nt = 0; nt < 4; nt++) {
            int c0 = wn + nt*8 + kq*2;
            if (r0 < Mrem) {
                float2 v = make_float2(acc[mt][nt][0], acc[mt][nt][1]);
                if (D) {
                    float2 d = *(const float2*)(D + (size_t)r0 * ldc + c0);
                    v.x += d.x; v.y += d.y;
                }
                if (ROUND) { v.x = to_tf32(v.x); v.y = to_tf32(v.y); }
                *(float2*)(C + (size_t)r0 * ldc + c0) = v;
            }
            int r1 = r0 + 8;
            if (r1 < Mrem) {
                float2 v = make_float2(acc[mt][nt][2], acc[mt][nt][3]);
                if (D) {
                    float2 d = *(const float2*)(D + (size_t)r1 * ldc + c0);
                    v.x += d.x; v.y += d.y;
                }
                if (ROUND) { v.x = to_tf32(v.x); v.y = to_tf32(v.y); }
                *(float2*)(C + (size_t)r1 * ldc + c0) = v;
            }
        }
    }
}

// ---------------- fused MoE gate+up+silu kernel --------------------------------
// act[slot][n] = tf32( silu(xg @ GwT^T) * (xg @ UwT^T) )
__global__ __launch_bounds__(256, 1)
void tc_moe_gu(const float* __restrict__ Ab,
               const float* __restrict__ Gt, const float* __restrict__ Ut,
               float* __restrict__ act,
               const int* __restrict__ offsets, const int* __restrict__ counts)
{
    int e = blockIdx.z;
    int cnt = counts[e];
    int m0 = blockIdx.y * 128;
    if (m0 >= cnt) return;
    int off = offsets[e];
    int n0 = blockIdx.x * 128;
    const int K = HH;
    int Mrem = cnt - m0;

    const float* A  = Ab + ((size_t)off + m0) * K;
    const float* Bg = Gt + (size_t)e * K * II + (size_t)n0 * K;
    const float* Bu = Ut + (size_t)e * K * II + (size_t)n0 * K;
    float* C = act + ((size_t)off + m0) * II + n0;

    extern __shared__ __align__(16) float smemf[];
    uint32_t sbase = smem_u32(smemf);
    int tid = threadIdx.x;
    int wid = tid >> 5;
    int lane = tid & 31;

    int ar  = tid >> 1;
    int ako = (tid & 1) * 8;
    int a_sz = (ar < Mrem) ? 16 : 0;
    const float* agbase = A + (size_t)ar * K + ako;
    const float* ggbase = Bg + (size_t)ar * K + ako;
    const float* ugbase = Bu + (size_t)ar * K + ako;
    uint32_t soff = (uint32_t)(ar * 16 + ako) * 4;

    int wm = (wid >> 2) * 64;
    int wn = (wid & 3) * 32;
    int qrow = lane >> 5 ? 0 : (lane >> 2);   // lane>>2 (0..7)
    qrow = lane >> 2;
    int kq4 = (lane & 3) * 4;

    float accg[4][4][4], accu[4][4][4];
    #pragma unroll
    for (int i = 0; i < 4; i++)
        #pragma unroll
        for (int j = 0; j < 4; j++)
            #pragma unroll
            for (int c = 0; c < 4; c++) { accg[i][j][c] = 0.f; accu[i][j][c] = 0.f; }

    const int KT = K >> 4;

    #pragma unroll
    for (int c = 0; c < NSTAGE - 1; c++) {
        int kc = c << 4;
        uint32_t ab = sbase + (uint32_t)c * (BSTG * 4);
        uint32_t gb = sbase + (uint32_t)(NSTAGE + c) * (BSTG * 4);
        uint32_t ub = sbase + (uint32_t)(2*NSTAGE + c) * (BSTG * 4);
        cp16(ab + soff,      agbase + kc,     a_sz);
        cp16(ab + soff + 16, agbase + kc + 4, a_sz);
        cp16(gb + soff,      ggbase + kc,     16);
        cp16(gb + soff + 16, ggbase + kc + 4, 16);
        cp16(ub + soff,      ugbase + kc,     16);
        cp16(ub + soff + 16, ugbase + kc + 4, 16);
        CP_COMMIT();
    }

    for (int kt = 0; kt < KT; kt++) {
        CP_WAIT(NSTAGE - 2);
        __syncthreads();

        int nc = kt + NSTAGE - 1;
        if (nc < KT) {
            int s = nc & (NSTAGE - 1);
            int kc = nc << 4;
            uint32_t ab = sbase + (uint32_t)s * (BSTG * 4);
            uint32_t gb = sbase + (uint32_t)(NSTAGE + s) * (BSTG * 4);
            uint32_t ub = sbase + (uint32_t)(2*NSTAGE + s) * (BSTG * 4);
            cp16(ab + soff,      agbase + kc,     a_sz);
            cp16(ab + soff + 16, agbase + kc + 4, a_sz);
            cp16(gb + soff,      ggbase + kc,     16);
            cp16(gb + soff + 16, ggbase + kc + 4, 16);
            cp16(ub + soff,      ugbase + kc,     16);
            cp16(ub + soff + 16, ugbase + kc + 4, 16);
        }
        CP_COMMIT();

        int s = kt & (NSTAGE - 1);
        const float* As = smemf + (size_t)s * BSTG;
        const float* Gs = smemf + (size_t)(NSTAGE + s) * BSTG;
        const float* Us = smemf + (size_t)(2*NSTAGE + s) * BSTG;

        float4 av0[4], av1[4], gv[4], uv[4];
        #pragma unroll
        for (int mt = 0; mt < 4; mt++) {
            const float* ab = As + (wm + mt*16 + qrow) * 16 + kq4;
            av0[mt] = *(const float4*)ab;
            av1[mt] = *(const float4*)(ab + 128);
        }
        #pragma unroll
        for (int nt = 0; nt < 4; nt++) {
            gv[nt] = *(const float4*)(Gs + (wn + nt*8 + qrow) * 16 + kq4);
            uv[nt] = *(const float4*)(Us + (wn + nt*8 + qrow) * 16 + kq4);
        }

        #pragma unroll
        for (int mt = 0; mt < 4; mt++) {
            uint32_t afr[4] = { __float_as_uint(av0[mt].x), __float_as_uint(av1[mt].x),
                                __float_as_uint(av0[mt].y), __float_as_uint(av1[mt].y) };
            #pragma unroll
            for (int nt = 0; nt < 4; nt++) {
                uint32_t gfr[2] = { __float_as_uint(gv[nt].x), __float_as_uint(gv[nt].y) };
                uint32_t ufr[2] = { __float_as_uint(uv[nt].x), __float_as_uint(uv[nt].y) };
                mma_tf32(accg[mt][nt], afr, gfr);
                mma_tf32(accu[mt][nt], afr, ufr);
            }
        }
        #pragma unroll
        for (int mt = 0; mt < 4; mt++) {
            uint32_t afr[4] = { __float_as_uint(av0[mt].z), __float_as_uint(av1[mt].z),
                                __float_as_uint(av0[mt].w), __float_as_uint(av1[mt].w) };
            #pragma unroll
            for (int nt = 0; nt < 4; nt++) {
                uint32_t gfr[2] = { __float_as_uint(gv[nt].z), __float_as_uint(gv[nt].w) };
                uint32_t ufr[2] = { __float_as_uint(uv[nt].z), __float_as_uint(uv[nt].w) };
                mma_tf32(accg[mt][nt], afr, gfr);
                mma_tf32(accu[mt][nt], afr, ufr);
            }
        }
    }

    int kq = lane & 3;
    #pragma unroll
    for (int mt = 0; mt < 4; mt++) {
        int r0 = wm + mt*16 + qrow;
        #pragma unroll
        for (int nt = 0; nt < 4; nt++) {
            int c0 = wn + nt*8 + kq*2;
            if (r0 < Mrem) {
                float g0 = accg[mt][nt][0], g1 = accg[mt][nt][1];
                float a0 = g0 / (1.f + __expf(-g0)) * accu[mt][nt][0];
                float a1 = g1 / (1.f + __expf(-g1)) * accu[mt][nt][1];
                *(float2*)(C + (size_t)r0 * II + c0) = make_float2(to_tf32(a0), to_tf32(a1));
            }
            int r1 = r0 + 8;
            if (r1 < Mrem) {
                float g2 = accg[mt][nt][2], g3 = accg[mt][nt][3];
                float a2 = g2 / (1.f + __expf(-g2)) * accu[mt][nt][2];
                float a3 = g3 / (1.f + __expf(-g3)) * accu[mt][nt][3];
                *(float2*)(C + (size_t)r1 * II + c0) = make_float2(to_tf32(a2), to_tf32(a3));
            }
        }
    }
}

// ---------------- GEMM wrappers ------------------------------------------------
__global__ __launch_bounds__(256, 2)
void tc_gemm(const float* __restrict__ A, const float* __restrict__ Bt,
             const float* __restrict__ D, float* __restrict__ C, int M, int N, int K)
{
    int m0 = blockIdx.y * 128, n0 = blockIdx.x * 128;
    mma_core<false>(A + (size_t)m0 * K, K, M - m0,
                    Bt + (size_t)n0 * K, K,
                    D ? D + (size_t)m0 * N + n0 : (const float*)0,
                    C + (size_t)m0 * N + n0, N, K);
}

__global__ __launch_bounds__(256, 2)
void tc_scores(const float* __restrict__ q, const float* __restrict__ k,
               float* __restrict__ scores)
{
    int z = blockIdx.z, b = z >> 4, h = z & 15;
    int m0 = blockIdx.y * 128, n0 = blockIdx.x * 128;
    if (n0 >= m0 + 128) return;  // causal skip
    const float* A  = q + (size_t)b * SS * QD + (size_t)h * HD + (size_t)m0 * QD;
    const float* Bp = k + (size_t)b * SS * KVD + (size_t)(h >> 2) * HD + (size_t)n0 * KVD;
    float* C = scores + (size_t)z * SS * SS + (size_t)m0 * SS + n0;
    mma_core<false>(A, QD, 128, Bp, KVD, (const float*)0, C, SS, HD);
}

__global__ __launch_bounds__(256, 2)
void tc_pv(const float* __restrict__ P, const float* __restrict__ vt,
           float* __restrict__ attn)
{
    int z = blockIdx.z, b = z >> 4, h = z & 15;
    int m0 = blockIdx.y * 128;
    const float* A  = P + (size_t)z * SS * SS + (size_t)m0 * SS;
    const float* Bp = vt + ((size_t)(b * NKV + (h >> 2)) * HD) * SS;  // [d][s]
    float* C = attn + (size_t)b * SS * QD + (size_t)h * HD + (size_t)m0 * QD;
    mma_core<true>(A, SS, 128, Bp, SS, (const float*)0, C, QD, m0 + 128);
}

__global__ __launch_bounds__(256, 2)
void tc_moe(const float* __restrict__ Ab, const float* __restrict__ Wt,
            float* __restrict__ out,
            const int* __restrict__ offsets, const int* __restrict__ counts, int N, int K)
{
    int e = blockIdx.z;
    int cnt = counts[e];
    int m0 = blockIdx.y * 128;
    if (m0 >= cnt) return;
    int off = offsets[e];
    int n0 = blockIdx.x * 128;
    mma_core<false>(Ab + ((size_t)off + m0) * K, K, cnt - m0,
                    Wt + (size_t)e * K * N + (size_t)n0 * K, K, (const float*)0,
                    out + ((size_t)off + m0) * N + n0, N, K);
}

// ---------------- transpose kernels (round to tf32 on store) -------------------
__global__ void transpose_kernel(const float* __restrict__ src, float* __restrict__ dst,
                                 int srcRS, int dstRS, size_t srcBatch, size_t dstBatch)
{
    __shared__ float t[32][33];
    int z = blockIdx.z;
    src += (size_t)z * srcBatch;
    dst += (size_t)z * dstBatch;
    int c0 = blockIdx.x * 32, r0 = blockIdx.y * 32;
    int tx = threadIdx.x & 31, ty = threadIdx.x >> 5;
    #pragma unroll
    for (int i = 0; i < 4; i++)
        t[ty + i*8][tx] = src[(size_t)(r0 + ty + i*8) * srcRS + c0 + tx];
    __syncthreads();
    #pragma unroll
    for (int i = 0; i < 4; i++)
        dst[(size_t)(c0 + ty + i*8) * dstRS + r0 + tx] = to_tf32(t[tx][ty + i*8]);
}

__global__ void v_transpose_kernel(const float* __restrict__ v, float* __restrict__ vt)
{
    __shared__ float t[32][33];
    int z = blockIdx.z;                 // b*NKV + hk
    int b = z >> 2, hk = z & 3;
    const float* src = v + (size_t)b * SS * KVD + (size_t)hk * HD;   // [s][d], stride KVD
    float* dst = vt + (size_t)z * HD * SS;                           // [d][s], stride SS
    int c0 = blockIdx.x * 32, r0 = blockIdx.y * 32;
    int tx = threadIdx.x & 31, ty = threadIdx.x >> 5;
    #pragma unroll
    for (int i = 0; i < 4; i++)
        t[ty + i*8][tx] = src[(size_t)(r0 + ty + i*8) * KVD + c0 + tx];
    __syncthreads();
    #pragma unroll
    for (int i = 0; i < 4; i++)
        dst[(size_t)(c0 + ty + i*8) * SS + r0 + tx] = to_tf32(t[tx][ty + i*8]);
}

// ---------------- small kernels ------------------------------------------------
__global__ void zero_counts_kernel(int* counts) {
    if (threadIdx.x < NE) counts[threadIdx.x] = 0;
}

__global__ void rmsnorm_kernel(const float* __restrict__ in, const float* __restrict__ w,
                               float* __restrict__ out) {
    int t = blockIdx.x;
    const float* row = in + (size_t)t * HH;
    float ss = 0.f;
    for (int h = threadIdx.x; h < HH; h += 256) { float v = row[h]; ss += v * v; }
    __shared__ float red[256];
    red[threadIdx.x] = ss; __syncthreads();
    for (int s = 128; s > 0; s >>= 1) {
        if (threadIdx.x < s) red[threadIdx.x] += red[threadIdx.x + s];
        __syncthreads();
    }
    float scale = rsqrtf(red[0] / (float)HH + 1e-5f);
    for (int h = threadIdx.x; h < HH; h += 256)
        out[(size_t)t * HH + h] = to_tf32(row[h] * scale * w[h]);
}

__global__ void rope_kernel(float* __restrict__ q, int nheads, int total) {
    int idx = blockIdx.x * blockDim.x + threadIdx.x;
    if (idx >= total) return;
    int d = idx & 63;
    int rest = idx >> 6;
    int head = rest % nheads;
    int t = rest / nheads;
    int s = t & (SS - 1);
    float inv = __powf(10000.f, -(float)d / 64.f);
    float ang = (float)s * inv;
    float c, si; __sincosf(ang, &si, &c);
    size_t base = (size_t)t * nheads * HD + (size_t)head * HD + d;
    float x1 = q[base], x2 = q[base + 64];
    q[base]      = to_tf32(x1 * c - x2 * si);
    q[base + 64] = to_tf32(x2 * c + x1 * si);
}

__global__ void softmax_kernel(float* __restrict__ scores) {
    int z = blockIdx.y, m = blockIdx.x;
    float* row = scores + (size_t)z * SS * SS + (size_t)m * SS;
    int n = m + 1;
    const float scale = 0.08838834764831845f; // 1/sqrt(128)
    __shared__ float red[256];
    float mx = -3.4e38f;
    for (int j = threadIdx.x; j < n; j += 256) mx = fmaxf(mx, row[j]);
    red[threadIdx.x] = mx; __syncthreads();
    for (int s = 128; s > 0; s >>= 1) {
        if (threadIdx.x < s) red[threadIdx.x] = fmaxf(red[threadIdx.x], red[threadIdx.x + s]);
        __syncthreads();
    }
    mx = red[0]; __syncthreads();
    float sum = 0.f;
    for (int j = threadIdx.x; j < n; j += 256) {
        float p = __expf((row[j] - mx) * scale);
        row[j] = p;
        sum += p;
    }
    red[threadIdx.x] = sum; __syncthreads();
    for (int s = 128; s > 0; s >>= 1) {
        if (threadIdx.x < s) red[threadIdx.x] += red[threadIdx.x + s];
        __syncthreads();
    }
    float inv = 1.f / red[0];
    for (int j = threadIdx.x; j < n; j += 256) row[j] = to_tf32(row[j] * inv);
    int bound = ((m >> 7) + 1) << 7;
    for (int j = n + threadIdx.x; j < bound; j += 256) row[j] = 0.f;
}

__global__ void router_kernel(const float* __restrict__ x, const float* __restrict__ rw,
                              int* __restrict__ topi, float* __restrict__ topw,
                              int* __restrict__ counts)
{
    int t = blockIdx.x;
    const float* row = x + (size_t)t * HH;
    float acc[NE] = {};
    for (int h = threadIdx.x; h < HH; h += 256) {
        float v = row[h];
        const float* r = rw + (size_t)h * NE;
        #pragma unroll
        for (int e = 0; e < NE; e++) acc[e] += v * r[e];
    }
    __shared__ float red[256];
    __shared__ float logits[NE];
    for (int e = 0; e < NE; e++) {
        red[threadIdx.x] = acc[e]; __syncthreads();
        for (int s = 128; s > 0; s >>= 1) {
            if (threadIdx.x < s) red[threadIdx.x] += red[threadIdx.x + s];
            __syncthreads();
        }
        if (threadIdx.x == 0) logits[e] = red[0];
        __syncthreads();
    }
    if (threadIdx.x == 0) {
        float mx = logits[0];
        for (int e = 1; e < NE; e++) mx = fmaxf(mx, logits[e]);
        float p[NE];
        for (int e = 0; e < NE; e++) p[e] = __expf(logits[e] - mx);
        int i1 = 0;
        for (int e = 1; e < NE; e++) if (p[e] > p[i1]) i1 = e;
        int i2 = (i1 == 0) ? 1 : 0;
        for (int e = 0; e < NE; e++) if (e != i1 && p[e] > p[i2]) i2 = e;
        float w1 = p[i1], w2 = p[i2];
        float inv = 1.f / (w1 + w2);
        topi[t * 2] = i1;  topi[t * 2 + 1] = i2;
        topw[t * 2] = w1 * inv;  topw[t * 2 + 1] = w2 * inv;
        atomicAdd(&counts[i1], 1);
        atomicAdd(&counts[i2], 1);
    }
}

__global__ void scan_kernel(const int* __restrict__ counts, int* __restrict__ offsets,
                            int* __restrict__ cursor) {
    if (threadIdx.x == 0) {
        int o = 0;
        for (int e = 0; e < NE; e++) { offsets[e] = o; cursor[e] = o; o += counts[e]; }
    }
}

__global__ void scatter_kernel(const int* __restrict__ topi, int* __restrict__ cursor,
                               int* __restrict__ tok, int* __restrict__ slot) {
    int t = blockIdx.x * blockDim.x + threadIdx.x;
    if (t >= TT) return;
    for (int j = 0; j < 2; j++) {
        int e = topi[t * 2 + j];
        int s = atomicAdd(&cursor[e], 1);
        tok[s] = t;
        slot[t * 2 + j] = s;
    }
}

__global__ void gather_kernel(const float* __restrict__ x, const int* __restrict__ tok,
                              float* __restrict__ xg) {
    size_t idx = (size_t)blockIdx.x * blockDim.x + threadIdx.x;
    int slot = (int)(idx >> 11);
    int h = (int)(idx & (HH - 1));
    xg[idx] = x[(size_t)tok[slot] * HH + h];
}

__global__ void combine_kernel(const float* __restrict__ hid2, const float* __restrict__ y,
                               const int* __restrict__ slot, const float* __restrict__ topw,
                               float* __restrict__ out)
{
    size_t idx = (size_t)blockIdx.x * blockDim.x + threadIdx.x;
    int t = (int)(idx >> 11);
    int h = (int)(idx & (HH - 1));
    int s0 = slot[t * 2], s1 = slot[t * 2 + 1];
    float w0 = topw[t * 2], w1 = topw[t * 2 + 1];
    out[idx] = hid2[idx] + w0 * y[(size_t)s0 * HH + h] + w1 * y[(size_t)s1 * HH + h];
}

// ---------------- launch -------------------------------------------------------
extern "C" void kernel_launch(void* const* d_in, const int* in_sizes, int n_in,
                              void* d_out, int out_size)
{
    const float* hs  = (const float*)d_in[0];
    const float* ln1 = (const float*)d_in[1];
    const float* ln2 = (const float*)d_in[2];
    const float* wq  = (const float*)d_in[3];
    const float* wk  = (const float*)d_in[4];
    const float* wv  = (const float*)d_in[5];
    const float* wo  = (const float*)d_in[6];
    const float* rw  = (const float*)d_in[7];
    const float* gw  = (const float*)d_in[8];
    const float* uw  = (const float*)d_in[9];
    const float* dw  = (const float*)d_in[10];
    float* out = (float*)d_out;

    float *px, *pq, *pk, *pv, *pscores, *pattn, *phid2, *pxg, *pact, *py, *ptopw;
    float *pwqT, *pwkT, *pwvT, *pwoT, *pgwT, *puwT, *pdwT, *pvT;
    int *ptopi, *pcounts, *poffsets, *pcursor, *ptok, *pslot;
    cudaGetSymbolAddress((void**)&px, g_x);
    cudaGetSymbolAddress((void**)&pq, g_q);
    cudaGetSymbolAddress((void**)&pk, g_k);
    cudaGetSymbolAddress((void**)&pv, g_v);
    cudaGetSymbolAddress((void**)&pscores, g_scores);
    cudaGetSymbolAddress((void**)&pattn, g_attn);
    cudaGetSymbolAddress((void**)&phid2, g_hid2);
    cudaGetSymbolAddress((void**)&pxg, g_xg);
    cudaGetSymbolAddress((void**)&pact, g_act);
    cudaGetSymbolAddress((void**)&py, g_y);
    cudaGetSymbolAddress((void**)&ptopi, g_topi);
    cudaGetSymbolAddress((void**)&ptopw, g_topw);
    cudaGetSymbolAddress((void**)&pcounts, g_counts);
    cudaGetSymbolAddress((void**)&poffsets, g_offsets);
    cudaGetSymbolAddress((void**)&pcursor, g_cursor);
    cudaGetSymbolAddress((void**)&ptok, g_tok);
    cudaGetSymbolAddress((void**)&pslot, g_slot);
    cudaGetSymbolAddress((void**)&pwqT, g_wqT);
    cudaGetSymbolAddress((void**)&pwkT, g_wkT);
    cudaGetSymbolAddress((void**)&pwvT, g_wvT);
    cudaGetSymbolAddress((void**)&pwoT, g_woT);
    cudaGetSymbolAddress((void**)&pgwT, g_gwT);
    cudaGetSymbolAddress((void**)&puwT, g_uwT);
    cudaGetSymbolAddress((void**)&pdwT, g_dwT);
    cudaGetSymbolAddress((void**)&pvT, g_vT);

    cudaFuncSetAttribute(tc_gemm,   cudaFuncAttributeMaxDynamicSharedMemorySize, TC_SMEM_BYTES);
    cudaFuncSetAttribute(tc_scores, cudaFuncAttributeMaxDynamicSharedMemorySize, TC_SMEM_BYTES);
    cudaFuncSetAttribute(tc_pv,     cudaFuncAttributeMaxDynamicSharedMemorySize, TC_SMEM_BYTES);
    cudaFuncSetAttribute(tc_moe,    cudaFuncAttributeMaxDynamicSharedMemorySize, TC_SMEM_BYTES);
    cudaFuncSetAttribute(tc_moe_gu, cudaFuncAttributeMaxDynamicSharedMemorySize, GU_SMEM_BYTES);

    // weight transposes (+tf32 preround)
    transpose_kernel<<<dim3(QD/32, HH/32, 1), 256>>>(wq, pwqT, QD, HH, 0, 0);
    transpose_kernel<<<dim3(KVD/32, HH/32, 1), 256>>>(wk, pwkT, KVD, HH, 0, 0);
    transpose_kernel<<<dim3(KVD/32, HH/32, 1), 256>>>(wv, pwvT, KVD, HH, 0, 0);
    transpose_kernel<<<dim3(HH/32, QD/32, 1), 256>>>(wo, pwoT, HH, QD, 0, 0);
    transpose_kernel<<<dim3(II/32, HH/32, NE), 256>>>(gw, pgwT, II, HH, (size_t)HH*II, (size_t)II*HH);
    transpose_kernel<<<dim3(II/32, HH/32, NE), 256>>>(uw, puwT, II, HH, (size_t)HH*II, (size_t)II*HH);
    transpose_kernel<<<dim3(HH/32, II/32, NE), 256>>>(dw, pdwT, HH, II, (size_t)II*HH, (size_t)HH*II);

    zero_counts_kernel<<<1, 32>>>(pcounts);
    rmsnorm_kernel<<<TT, 256>>>(hs, ln1, px);

    tc_gemm<<<dim3(QD/128,  TT/128), 256, TC_SMEM_BYTES>>>(px, pwqT, nullptr, pq, TT, QD,  HH);
    tc_gemm<<<dim3(KVD/128, TT/128), 256, TC_SMEM_BYTES>>>(px, pwkT, nullptr, pk, TT, KVD, HH);
    tc_gemm<<<dim3(KVD/128, TT/128), 256, TC_SMEM_BYTES>>>(px, pwvT, nullptr, pv, TT, KVD, HH);

    rope_kernel<<<(TT*NH*64)/256, 256>>>(pq, NH, TT*NH*64);
    rope_kernel<<<(TT*NKV*64)/256, 256>>>(pk, NKV, TT*NKV*64);
    v_transpose_kernel<<<dim3(HD/32, SS/32, BB*NKV), 256>>>(pv, pvT);

    tc_scores<<<dim3(SS/128, SS/128, BB*NH), 256, TC_SMEM_BYTES>>>(pq, pk, pscores);
    softmax_kernel<<<dim3(SS, BB*NH), 256>>>(pscores);
    tc_pv<<<dim3(1, SS/128, BB*NH), 256, TC_SMEM_BYTES>>>(pscores, pvT, pattn);

    tc_gemm<<<dim3(HH/128, TT/128), 256, TC_SMEM_BYTES>>>(pattn, pwoT, hs, phid2, TT, HH, QD);

    rmsnorm_kernel<<<TT, 256>>>(phid2, ln2, px);
    router_kernel<<<TT, 256>>>(px, rw, ptopi, ptopw, pcounts);
    scan_kernel<<<1, 32>>>(pcounts, poffsets, pcursor);
    scatter_kernel<<<TT/256, 256>>>(ptopi, pcursor, ptok, pslot);
    gather_kernel<<<(int)(((size_t)NSLOTS*HH)/256), 256>>>(px, ptok, pxg);

    tc_moe_gu<<<dim3(II/128, NSLOTS/128, NE), 256, GU_SMEM_BYTES>>>(pxg, pgwT, puwT, pact, poffsets, pcounts);
    tc_moe<<<dim3(HH/128, NSLOTS/128, NE), 256, TC_SMEM_BYTES>>>(pact, pdwT, py, poffsets, pcounts, HH, II);

    combine_kernel<<<(int)(((size_t)TT*HH)/256), 256>>>(phid2, py, pslot, ptopw, out);
}